// round 1
// baseline (speedup 1.0000x reference)
#include <cuda_runtime.h>
#include <cstdint>

#define N_NODES 50000
#define N_EDGES 800000
#define DIM     128

// ---------------- scratch (device globals; no allocation allowed) ----------------
__device__ float g_xbuf[N_NODES * DIM];   // current node features
__device__ float g_h   [N_NODES * DIM];   // hidden / predictor A
__device__ float g_aggr[N_NODES * DIM];   // message aggregation
__device__ float g_B   [N_NODES * DIM];   // predictor B
__device__ int   g_src [N_EDGES];
__device__ int   g_dst [N_EDGES];
__device__ int   g_is64;

__device__ __forceinline__ float* bufptr(int id) {
    switch (id) {
        case 0:  return g_xbuf;
        case 1:  return g_h;
        case 2:  return g_aggr;
        default: return g_B;
    }
}

// ---------------- dtype detect + index normalize ----------------
// If edge_index is int64 (little-endian), every odd 32-bit word of the first 64
// pairs is a zero high-half (indices < 50000). If int32, odd words are real
// indices (P[all 64 == 0] ~ 0 for random data).
__global__ void k_detect(const void* ei) {
    __shared__ int s;
    if (threadIdx.x == 0) s = 0;
    __syncthreads();
    const unsigned* w = (const unsigned*)ei;
    if (w[2 * threadIdx.x + 1] != 0u) atomicOr(&s, 1);
    __syncthreads();
    if (threadIdx.x == 0) g_is64 = (s == 0) ? 1 : 0;
}

__global__ void k_convert(const void* ei) {
    int i = blockIdx.x * blockDim.x + threadIdx.x;
    if (i >= N_EDGES) return;
    if (g_is64) {
        const long long* p = (const long long*)ei;
        g_src[i] = (int)p[i];
        g_dst[i] = (int)p[N_EDGES + i];
    } else {
        const int* p = (const int*)ei;
        g_src[i] = p[i];
        g_dst[i] = p[N_EDGES + i];
    }
}

// ---------------- utility kernels ----------------
__global__ void k_copy_x(const float4* __restrict__ x) {
    float4* o = (float4*)g_xbuf;
    int total = N_NODES * DIM / 4;
    for (int i = blockIdx.x * blockDim.x + threadIdx.x; i < total;
         i += gridDim.x * blockDim.x)
        o[i] = x[i];
}

__global__ void k_zero_aggr() {
    float4* o = (float4*)g_aggr;
    float4 z = make_float4(0.f, 0.f, 0.f, 0.f);
    int total = N_NODES * DIM / 4;
    for (int i = blockIdx.x * blockDim.x + threadIdx.x; i < total;
         i += gridDim.x * blockDim.x)
        o[i] = z;
}

// ---------------- edge message + scatter-add ----------------
// msg = relu(x[src] + ea*We + be); aggr[dst] += msg   (vector RED, 1 warp/edge)
__global__ void k_edge_msg(const float* __restrict__ ea,
                           const float* __restrict__ We,
                           const float* __restrict__ be) {
    int gt   = blockIdx.x * blockDim.x + threadIdx.x;
    int warp = gt >> 5;
    int lane = gt & 31;
    int nw   = (gridDim.x * blockDim.x) >> 5;

    float4 wv = ((const float4*)We)[lane];
    float4 bv = ((const float4*)be)[lane];

    for (int e = warp; e < N_EDGES; e += nw) {
        int   s = g_src[e];
        int   d = g_dst[e];
        float a = __ldg(ea + e);
        float4 x = ((const float4*)(g_xbuf + (size_t)s * DIM))[lane];
        float4 m;
        m.x = fmaxf(x.x + fmaf(a, wv.x, bv.x), 0.f);
        m.y = fmaxf(x.y + fmaf(a, wv.y, bv.y), 0.f);
        m.z = fmaxf(x.z + fmaf(a, wv.z, bv.z), 0.f);
        m.w = fmaxf(x.w + fmaf(a, wv.w, bv.w), 0.f);
        float* p = g_aggr + (size_t)d * DIM + lane * 4;
        asm volatile("red.global.add.v4.f32 [%0], {%1,%2,%3,%4};"
                     :: "l"(p), "f"(m.x), "f"(m.y), "f"(m.z), "f"(m.w)
                     : "memory");
    }
}

// ---------------- 128x128 GEMM, thread-per-row, W in smem ----------------
// out[row] = act( (A[row] (+ Add[row])) @ W + bias )
__global__ void __launch_bounds__(128)
k_gemm128(int ia, int iadd, const float* __restrict__ W,
          const float* __restrict__ bias, int io, int relu, int nrows) {
    extern __shared__ float sW[];  // 128*128 floats = 64 KB
    const float4* Wv  = (const float4*)W;
    float4*       sWv = (float4*)sW;
    #pragma unroll
    for (int i = 0; i < 32; i++)
        sWv[i * 128 + threadIdx.x] = Wv[i * 128 + threadIdx.x];
    __syncthreads();

    int row = blockIdx.x * 128 + threadIdx.x;
    if (row >= nrows) return;

    const float* A   = bufptr(ia);
    float*       out = bufptr(io);

    float in[DIM];
    {
        const float4* a4 = (const float4*)(A + (size_t)row * DIM);
        #pragma unroll
        for (int k4 = 0; k4 < 32; k4++) {
            float4 v = a4[k4];
            in[4 * k4 + 0] = v.x; in[4 * k4 + 1] = v.y;
            in[4 * k4 + 2] = v.z; in[4 * k4 + 3] = v.w;
        }
        if (iadd >= 0) {
            const float4* b4 = (const float4*)(bufptr(iadd) + (size_t)row * DIM);
            #pragma unroll
            for (int k4 = 0; k4 < 32; k4++) {
                float4 v = b4[k4];
                in[4 * k4 + 0] += v.x; in[4 * k4 + 1] += v.y;
                in[4 * k4 + 2] += v.z; in[4 * k4 + 3] += v.w;
            }
        }
    }

    float4* o4 = (float4*)(out + (size_t)row * DIM);
    #pragma unroll 1
    for (int j0 = 0; j0 < DIM; j0 += 8) {
        float acc[8];
        #pragma unroll
        for (int jj = 0; jj < 8; jj++)
            acc[jj] = bias ? __ldg(bias + j0 + jj) : 0.f;
        #pragma unroll
        for (int k = 0; k < DIM; k++) {
            float av = in[k];
            #pragma unroll
            for (int jj = 0; jj < 8; jj++)
                acc[jj] = fmaf(av, sW[k * DIM + j0 + jj], acc[jj]);
        }
        if (relu) {
            #pragma unroll
            for (int jj = 0; jj < 8; jj++) acc[jj] = fmaxf(acc[jj], 0.f);
        }
        o4[j0 / 4]     = make_float4(acc[0], acc[1], acc[2], acc[3]);
        o4[j0 / 4 + 1] = make_float4(acc[4], acc[5], acc[6], acc[7]);
    }
}

// ---------------- edge predictor epilogue ----------------
// out[e] = relu(A[src] + B[dst] + bp1) . Wp2 + bp2   (1 warp/edge)
__global__ void k_edge_pred(const float* __restrict__ bp1,
                            const float* __restrict__ Wp2,
                            const float* __restrict__ bp2,
                            float* __restrict__ out) {
    int gt   = blockIdx.x * blockDim.x + threadIdx.x;
    int warp = gt >> 5;
    int lane = gt & 31;
    int nw   = (gridDim.x * blockDim.x) >> 5;

    float4 b1 = ((const float4*)bp1)[lane];
    float4 w2 = ((const float4*)Wp2)[lane];
    float  b2 = __ldg(bp2);

    for (int e = warp; e < N_EDGES; e += nw) {
        int s = g_src[e];
        int d = g_dst[e];
        float4 av = ((const float4*)(g_h + (size_t)s * DIM))[lane];
        float4 bv = ((const float4*)(g_B + (size_t)d * DIM))[lane];
        float p = 0.f;
        p = fmaf(fmaxf(av.x + bv.x + b1.x, 0.f), w2.x, p);
        p = fmaf(fmaxf(av.y + bv.y + b1.y, 0.f), w2.y, p);
        p = fmaf(fmaxf(av.z + bv.z + b1.z, 0.f), w2.z, p);
        p = fmaf(fmaxf(av.w + bv.w + b1.w, 0.f), w2.w, p);
        #pragma unroll
        for (int o = 16; o > 0; o >>= 1)
            p += __shfl_xor_sync(0xffffffffu, p, o);
        if (lane == 0) out[e] = p + b2;
    }
}

// ---------------- launch ----------------
extern "C" void kernel_launch(void* const* d_in, const int* in_sizes, int n_in,
                              void* d_out, int out_size) {
    const float* x   = (const float*)d_in[0];
    const float* ea  = (const float*)d_in[1];
    const void*  ei  = d_in[2];
    const float* Wl1 = (const float*)d_in[3];
    const float* bl1 = (const float*)d_in[4];
    const float* Wl2 = (const float*)d_in[5];
    const float* bl2 = (const float*)d_in[6];
    const float* We  = (const float*)d_in[7];
    const float* be  = (const float*)d_in[8];
    const float* Wp1 = (const float*)d_in[9];
    const float* bp1 = (const float*)d_in[10];
    const float* Wp2 = (const float*)d_in[11];
    const float* bp2 = (const float*)d_in[12];
    float* out = (float*)d_out;

    cudaFuncSetAttribute(k_gemm128, cudaFuncAttributeMaxDynamicSharedMemorySize,
                         DIM * DIM * (int)sizeof(float));

    const int GEMM_SMEM  = DIM * DIM * (int)sizeof(float);
    const int GEMM_GRID  = (N_NODES + 127) / 128;      // 391
    const int EDGE_GRID  = 1184;                       // 148 SMs * 8 blocks
    const int CONV_GRID  = (N_EDGES + 255) / 256;

    k_detect<<<1, 64>>>(ei);
    k_convert<<<CONV_GRID, 256>>>(ei);
    k_copy_x<<<2048, 256>>>((const float4*)x);

    for (int l = 0; l < 3; l++) {
        k_zero_aggr<<<2048, 256>>>();
        k_edge_msg<<<EDGE_GRID, 256>>>(ea, We + l * DIM, be + l * DIM);
        // h = relu((x + aggr) @ Wl1 + bl1)
        k_gemm128<<<GEMM_GRID, 128, GEMM_SMEM>>>(0, 2, Wl1 + l * DIM * DIM,
                                                 bl1 + l * DIM, 1, 1, N_NODES);
        // x = relu(h @ Wl2 + bl2)
        k_gemm128<<<GEMM_GRID, 128, GEMM_SMEM>>>(1, -1, Wl2 + l * DIM * DIM,
                                                 bl2 + l * DIM, 0, 1, N_NODES);
    }

    // A = x @ Wp1[0:128]  (into g_h),  B = x @ Wp1[128:256] (into g_B)
    k_gemm128<<<GEMM_GRID, 128, GEMM_SMEM>>>(0, -1, Wp1, nullptr, 1, 0, N_NODES);
    k_gemm128<<<GEMM_GRID, 128, GEMM_SMEM>>>(0, -1, Wp1 + DIM * DIM, nullptr, 3, 0, N_NODES);

    k_edge_pred<<<EDGE_GRID, 256>>>(bp1, Wp2, bp2, out);
}